// round 14
// baseline (speedup 1.0000x reference)
#include <cuda_runtime.h>
#include <cuda_bf16.h>

#define NPART 2048
#define HID 32
#define CUTOFF 2.5f
#define CUTOFF2 6.25f
#define M_TAB 2048

#define NCELL 5
#define NCELL3 125          // 5^3 cells, edge 13.7/5 = 2.74 >= cutoff
#define MAXC 64             // max atoms per cell (mean 16.4, 64 = mean + 12 sigma)
#define NSLOT 14            // self + 13 half-stencil neighbors
#define MAXLIST 512         // staged neighborhood capacity (expected ~230)
#define NSPLIT 4            // blocks per cell
#define NTHREADS 128

__device__ double g_energy_accum = 0.0;
__device__ unsigned int g_block_count = 0;
__device__ float g_table[M_TAB + 1];
__device__ float4 g_cell_pos[NCELL3][MAXC];
__device__ int g_cell_cnt[NCELL3];

// 13-offset half stencil: (dx,dy,dz) lexicographically positive by (dz,dy,dx)
__constant__ signed char c_off[13][3] = {
    { 1, 0, 0},
    {-1, 1, 0}, { 0, 1, 0}, { 1, 1, 0},
    {-1,-1, 1}, { 0,-1, 1}, { 1,-1, 1},
    {-1, 0, 1}, { 0, 0, 1}, { 1, 0, 1},
    {-1, 1, 1}, { 0, 1, 1}, { 1, 1, 1},
};

// Prep: energy lookup table (exact tanhf) + deterministic warp-per-cell binning.
__global__ void __launch_bounds__(NTHREADS) pp_prep_kernel(
    const float* __restrict__ xyz,
    const float* __restrict__ cell_diag,
    const float* __restrict__ W1,
    const float* __restrict__ b1,
    const float* __restrict__ W2,
    const float* __restrict__ b2)
{
    const int gtid = (int)blockIdx.x * NTHREADS + (int)threadIdx.x;
    const int w    = gtid >> 5;
    const int lane = gtid & 31;

    // ---- table ----
    if (gtid <= M_TAB) {
        const float d = (CUTOFF / (float)M_TAB) * (float)gtid;
        float e = __ldg(&b2[0]);
        #pragma unroll
        for (int k = 0; k < HID; ++k) {
            e = fmaf(__ldg(&W2[k]), tanhf(fmaf(d, __ldg(&W1[k]), __ldg(&b1[k]))), e);
        }
        g_table[gtid] = e;
    }

    // ---- binning: warp w owns cell w (deterministic, in atom-index order) ----
    if (w < NCELL3) {
        const float ix = (float)NCELL / __ldg(&cell_diag[0]);
        const float iy = (float)NCELL / __ldg(&cell_diag[1]);
        const float iz = (float)NCELL / __ldg(&cell_diag[2]);
        int cnt = 0;
        for (int base = 0; base < NPART; base += 32) {
            const int j = base + lane;               // NPART % 32 == 0
            const float x = __ldg(&xyz[3 * j + 0]);
            const float y = __ldg(&xyz[3 * j + 1]);
            const float z = __ldg(&xyz[3 * j + 2]);
            const int cx = min(NCELL - 1, (int)(x * ix));
            const int cy = min(NCELL - 1, (int)(y * iy));
            const int cz = min(NCELL - 1, (int)(z * iz));
            const int cid = (cz * NCELL + cy) * NCELL + cx;
            const bool hit = (cid == w);
            const unsigned int bal = __ballot_sync(0xFFFFFFFFu, hit);
            if (hit) {
                const int pos = cnt + __popc(bal & ((1u << lane) - 1u));
                if (pos < MAXC) g_cell_pos[w][pos] = make_float4(x, y, z, 0.0f);
            }
            cnt += __popc(bal);
        }
        if (lane == 0) g_cell_cnt[w] = min(cnt, MAXC);
    }
}

__global__ void __launch_bounds__(NTHREADS) pp_pair_kernel(
    const float* __restrict__ cell_diag,
    float* __restrict__ out)
{
    __shared__ float4 sPos[MAXLIST];
    __shared__ int    sCid[NSLOT];
    __shared__ int    sCnt[NSLOT];
    __shared__ int    sOff[NSLOT + 1];
    __shared__ float  sRed[NTHREADS / 32];

    const int tid  = (int)threadIdx.x;
    const int warp = tid >> 5;
    const int lane = tid & 31;

    const int cell    = (int)blockIdx.x / NSPLIT;
    const int quarter = (int)blockIdx.x % NSPLIT;

    // ---- stage 1: slot cell ids + counts ----
    if (tid < NSLOT) {
        int cid;
        if (tid == 0) {
            cid = cell;                                  // self is slot 0
        } else {
            const int cx = cell % NCELL;
            const int cy = (cell / NCELL) % NCELL;
            const int cz = cell / (NCELL * NCELL);
            int nx = cx + c_off[tid - 1][0]; nx += (nx < 0) ? NCELL : 0; nx -= (nx >= NCELL) ? NCELL : 0;
            int ny = cy + c_off[tid - 1][1]; ny += (ny < 0) ? NCELL : 0; ny -= (ny >= NCELL) ? NCELL : 0;
            int nz = cz + c_off[tid - 1][2]; nz += (nz < 0) ? NCELL : 0; nz -= (nz >= NCELL) ? NCELL : 0;
            cid = (nz * NCELL + ny) * NCELL + nx;
        }
        sCid[tid] = cid;
        sCnt[tid] = g_cell_cnt[cid];
    }
    __syncthreads();

    if (tid == 0) {
        int o = 0;
        #pragma unroll
        for (int s = 0; s < NSLOT; ++s) {
            sOff[s] = o;
            o = min(MAXLIST, o + sCnt[s]);
        }
        sOff[NSLOT] = o;
    }
    __syncthreads();

    // ---- stage 2: copy neighborhood atoms into contiguous smem ----
    for (int s = warp; s < NSLOT; s += NTHREADS / 32) {
        const int cid = sCid[s];
        const int o   = sOff[s];
        const int n   = sOff[s + 1] - o;
        for (int k = lane; k < n; k += 32)
            sPos[o + k] = g_cell_pos[cid][k];
    }
    __syncthreads();

    const int nA = sOff[1];         // self-cell atom count (staged at offset 0)
    const int M  = sOff[NSLOT];     // total staged atoms

    const float Lx = __ldg(&cell_diag[0]);
    const float Ly = __ldg(&cell_diag[1]);
    const float Lz = __ldg(&cell_diag[2]);
    const float iLx = __frcp_rn(Lx), iLy = __frcp_rn(Ly), iLz = __frcp_rn(Lz);
    const float tscale = (float)M_TAB / CUTOFF;

    float acc = 0.0f;
    const int nchunk = (M + 31) >> 5;

    for (int a = quarter; a < nA; a += NSPLIT) {
        const float4 pa = sPos[a];
        for (int c = warp; c < nchunk; c += NTHREADS / 32) {
            const int b = (c << 5) + lane;
            if (b < M) {
                const float4 pb = sPos[b];
                float dx = pb.x - pa.x;
                float dy = pb.y - pa.y;
                float dz = pb.z - pa.z;
                dx = fmaf(-Lx, rintf(dx * iLx), dx);
                dy = fmaf(-Ly, rintf(dy * iLy), dy);
                dz = fmaf(-Lz, rintf(dz * iLz), dz);
                const float r2 = fmaf(dx, dx, fmaf(dy, dy, dz * dz));
                // triangular skip inside self cell (b indexes offset 0..nA-1)
                const bool tri = (b < nA) && (b <= a);
                if (!tri && r2 < CUTOFF2 && r2 > 0.0f) {
                    const float u = sqrtf(r2) * tscale;
                    const int   t = (int)u;
                    const float f = u - (float)t;
                    const float e0 = g_table[t];
                    const float e1 = g_table[t + 1];
                    acc += fmaf(e1 - e0, f, e0);
                }
            }
        }
    }

    // ---- reduction + finalize ----
    #pragma unroll
    for (int off = 16; off > 0; off >>= 1)
        acc += __shfl_xor_sync(0xFFFFFFFFu, acc, off);
    if (lane == 0) sRed[warp] = acc;
    __syncthreads();

    if (tid == 0) {
        float bsum = 0.0f;
        #pragma unroll
        for (int s = 0; s < NTHREADS / 32; ++s) bsum += sRed[s];
        atomicAdd(&g_energy_accum, (double)bsum);
        __threadfence();
        const unsigned int ticket = atomicAdd(&g_block_count, 1u);
        if (ticket == gridDim.x - 1) {
            const double total = atomicAdd(&g_energy_accum, 0.0);
            out[0] = (float)total;
            g_energy_accum = 0.0;
            g_block_count = 0;
            __threadfence();
        }
    }
}

extern "C" void kernel_launch(void* const* d_in, const int* in_sizes, int n_in,
                              void* d_out, int out_size) {
    const float* xyz       = (const float*)d_in[0];
    const float* cell_diag = (const float*)d_in[1];
    const float* W1        = (const float*)d_in[2];
    const float* b1        = (const float*)d_in[3];
    const float* W2        = (const float*)d_in[4];
    const float* b2        = (const float*)d_in[5];
    float* out = (float*)d_out;

    // 32 blocks x 128 = 4096 threads = 128 warps (>= 125 cells, >= 2049 table entries)
    pp_prep_kernel<<<32, NTHREADS>>>(xyz, cell_diag, W1, b1, W2, b2);
    pp_pair_kernel<<<NCELL3 * NSPLIT, NTHREADS>>>(cell_diag, out);
}

// round 15
// speedup vs baseline: 1.1928x; 1.1928x over previous
#include <cuda_runtime.h>
#include <cuda_bf16.h>

#define NPART 2048
#define HID 32
#define CUTOFF 2.5f
#define CUTOFF2 6.25f
#define M_TAB 2048

#define NCELL 5
#define NCELL3 125          // 5^3 cells, edge 13.7/5 = 2.74 >= cutoff
#define MAXC 64             // max atoms per cell (mean 16.4)
#define NSLOT 14            // self + 13 half-stencil neighbors
#define MAXLIST 384         // staged neighborhood capacity (expected ~230)
#define PT 256              // pair-kernel threads
#define PW 8                // pair-kernel warps

#define TBL_BLOCKS 9        // 9*256 = 2304 >= 2049 table entries
#define BIN_BLOCKS 16       // 16*8 = 128 warps >= 125 cells

__device__ double g_energy_accum = 0.0;
__device__ unsigned int g_block_count = 0;
__device__ float g_table[M_TAB + 1];
__device__ float4 g_cell_pos[NCELL3][MAXC];
__device__ int g_cell_cnt[NCELL3];

// 13-offset half stencil (S ∪ -S = 26 neighbors, S ∩ -S = ∅)
__constant__ signed char c_off[13][3] = {
    { 1, 0, 0},
    {-1, 1, 0}, { 0, 1, 0}, { 1, 1, 0},
    {-1,-1, 1}, { 0,-1, 1}, { 1,-1, 1},
    {-1, 0, 1}, { 0, 0, 1}, { 1, 0, 1},
    {-1, 1, 1}, { 0, 1, 1}, { 1, 1, 1},
};

__global__ void __launch_bounds__(256) pp_prep_kernel(
    const float* __restrict__ xyz,
    const float* __restrict__ cell_diag,
    const float* __restrict__ W1,
    const float* __restrict__ b1,
    const float* __restrict__ W2,
    const float* __restrict__ b2)
{
    const int blk = (int)blockIdx.x;

    if (blk < TBL_BLOCKS) {
        // ---- energy lookup table (exact tanhf) ----
        const int t = blk * 256 + (int)threadIdx.x;
        if (t <= M_TAB) {
            const float d = (CUTOFF / (float)M_TAB) * (float)t;
            float e = __ldg(&b2[0]);
            #pragma unroll
            for (int k = 0; k < HID; ++k) {
                e = fmaf(__ldg(&W2[k]), tanhf(fmaf(d, __ldg(&W1[k]), __ldg(&b1[k]))), e);
            }
            g_table[t] = e;
        }
        return;
    }

    // ---- binning: one warp per cell, deterministic (atom-index order) ----
    const int warp = (int)threadIdx.x >> 5;
    const int lane = (int)threadIdx.x & 31;
    const int w = (blk - TBL_BLOCKS) * 8 + warp;
    if (w >= NCELL3) return;

    const float ix = (float)NCELL / __ldg(&cell_diag[0]);
    const float iy = (float)NCELL / __ldg(&cell_diag[1]);
    const float iz = (float)NCELL / __ldg(&cell_diag[2]);

    int cnt = 0;
    for (int base = 0; base < NPART; base += 128) {   // 16 outer iters, 4-way batched
        float px[4], py[4], pz[4];
        int cid[4];
        #pragma unroll
        for (int u = 0; u < 4; ++u) {                 // 12 independent LDGs in flight
            const int j = base + u * 32 + lane;
            px[u] = __ldg(&xyz[3 * j + 0]);
            py[u] = __ldg(&xyz[3 * j + 1]);
            pz[u] = __ldg(&xyz[3 * j + 2]);
        }
        #pragma unroll
        for (int u = 0; u < 4; ++u) {
            const int cx = min(NCELL - 1, (int)(px[u] * ix));
            const int cy = min(NCELL - 1, (int)(py[u] * iy));
            const int cz = min(NCELL - 1, (int)(pz[u] * iz));
            cid[u] = (cz * NCELL + cy) * NCELL + cx;
        }
        #pragma unroll
        for (int u = 0; u < 4; ++u) {
            const bool hit = (cid[u] == w);
            const unsigned int bal = __ballot_sync(0xFFFFFFFFu, hit);
            if (hit) {
                const int pos = cnt + __popc(bal & ((1u << lane) - 1u));
                if (pos < MAXC)
                    g_cell_pos[w][pos] = make_float4(px[u], py[u], pz[u], 0.0f);
            }
            cnt += __popc(bal);
        }
    }
    if (lane == 0) g_cell_cnt[w] = min(cnt, MAXC);
}

__global__ void __launch_bounds__(PT) pp_pair_kernel(
    const float* __restrict__ cell_diag,
    float* __restrict__ out)
{
    __shared__ float4 sPos[MAXLIST];
    __shared__ int    sCid[NSLOT];
    __shared__ int    sCnt[NSLOT];
    __shared__ int    sOff[NSLOT + 1];
    __shared__ float  sRed[PW];

    const int tid  = (int)threadIdx.x;
    const int warp = tid >> 5;
    const int lane = tid & 31;
    const int cell = (int)blockIdx.x;

    // ---- slot cell ids + counts (threads 0..13) ----
    if (tid < NSLOT) {
        int cid;
        if (tid == 0) {
            cid = cell;                                  // self = slot 0 (offset 0)
        } else {
            const int cx = cell % NCELL;
            const int cy = (cell / NCELL) % NCELL;
            const int cz = cell / (NCELL * NCELL);
            int nx = cx + c_off[tid - 1][0]; nx += (nx < 0) ? NCELL : 0; nx -= (nx >= NCELL) ? NCELL : 0;
            int ny = cy + c_off[tid - 1][1]; ny += (ny < 0) ? NCELL : 0; ny -= (ny >= NCELL) ? NCELL : 0;
            int nz = cz + c_off[tid - 1][2]; nz += (nz < 0) ? NCELL : 0; nz -= (nz >= NCELL) ? NCELL : 0;
            cid = (nz * NCELL + ny) * NCELL + nx;
        }
        sCid[tid] = cid;
        sCnt[tid] = g_cell_cnt[cid];
    }
    __syncthreads();

    if (tid == 0) {
        int o = 0;
        #pragma unroll
        for (int s = 0; s < NSLOT; ++s) {
            sOff[s] = o;
            o = min(MAXLIST, o + sCnt[s]);
        }
        sOff[NSLOT] = o;
    }
    __syncthreads();

    // ---- stage neighborhood into contiguous smem (warp-per-slot) ----
    for (int s = warp; s < NSLOT; s += PW) {
        const int cid = sCid[s];
        const int o   = sOff[s];
        const int n   = sOff[s + 1] - o;
        for (int k = lane; k < n; k += 32)
            sPos[o + k] = g_cell_pos[cid][k];
    }
    __syncthreads();

    const int nA = sOff[1];
    const int M  = sOff[NSLOT];

    const float Lx = __ldg(&cell_diag[0]);
    const float Ly = __ldg(&cell_diag[1]);
    const float Lz = __ldg(&cell_diag[2]);
    const float iLx = __frcp_rn(Lx), iLy = __frcp_rn(Ly), iLz = __frcp_rn(Lz);
    const float tscale = (float)M_TAB / CUTOFF;

    float acc = 0.0f;

    for (int a = warp; a < nA; a += PW) {
        const float4 pa = sPos[a];
        for (int b0 = 0; b0 < M; b0 += 32) {
            const int b = b0 + lane;
            if (b < M) {
                const float4 pb = sPos[b];
                float dx = pb.x - pa.x;
                float dy = pb.y - pa.y;
                float dz = pb.z - pa.z;
                dx = fmaf(-Lx, rintf(dx * iLx), dx);
                dy = fmaf(-Ly, rintf(dy * iLy), dy);
                dz = fmaf(-Lz, rintf(dz * iLz), dz);
                const float r2 = fmaf(dx, dx, fmaf(dy, dy, dz * dz));
                const bool tri = (b < nA) && (b <= a);   // self-cell triangle skip
                if (!tri && r2 < CUTOFF2 && r2 > 0.0f) {
                    const float u = sqrtf(r2) * tscale;
                    const int   t = (int)u;
                    const float f = u - (float)t;
                    const float e0 = g_table[t];
                    const float e1 = g_table[t + 1];
                    acc += fmaf(e1 - e0, f, e0);
                }
            }
        }
    }

    // ---- reduction + last-block finalize ----
    #pragma unroll
    for (int off = 16; off > 0; off >>= 1)
        acc += __shfl_xor_sync(0xFFFFFFFFu, acc, off);
    if (lane == 0) sRed[warp] = acc;
    __syncthreads();

    if (tid == 0) {
        float bsum = 0.0f;
        #pragma unroll
        for (int s = 0; s < PW; ++s) bsum += sRed[s];
        atomicAdd(&g_energy_accum, (double)bsum);
        __threadfence();
        const unsigned int ticket = atomicAdd(&g_block_count, 1u);
        if (ticket == gridDim.x - 1) {
            const double total = atomicAdd(&g_energy_accum, 0.0);
            out[0] = (float)total;
            g_energy_accum = 0.0;
            g_block_count = 0;
            __threadfence();
        }
    }
}

extern "C" void kernel_launch(void* const* d_in, const int* in_sizes, int n_in,
                              void* d_out, int out_size) {
    const float* xyz       = (const float*)d_in[0];
    const float* cell_diag = (const float*)d_in[1];
    const float* W1        = (const float*)d_in[2];
    const float* b1        = (const float*)d_in[3];
    const float* W2        = (const float*)d_in[4];
    const float* b2        = (const float*)d_in[5];
    float* out = (float*)d_out;

    pp_prep_kernel<<<TBL_BLOCKS + BIN_BLOCKS, 256>>>(xyz, cell_diag, W1, b1, W2, b2);
    pp_pair_kernel<<<NCELL3, PT>>>(cell_diag, out);
}